// round 1
// baseline (speedup 1.0000x reference)
#include <cuda_runtime.h>
#include <math.h>

// Problem dims
constexpr int BB = 64;     // batch
constexpr int TT = 32;     // sentence len
constexpr int SS = 31;     // scan steps (T-1)
constexpr int VV = 10000;  // vocab
constexpr int EE = 300;    // embed dim
constexpr int HH = 256;    // hidden
constexpr int FF = 4096;   // input features
constexpr int GG = 1024;   // 4*H gates
constexpr int KIN = HH + EE; // 556
constexpr int MROWS = SS * BB; // 1984

// -------------------- device scratch (static, no allocs) --------------------
__device__ float d_Xp[BB * HH];                 // fc1 output
__device__ float d_xpart[16 * BB * HH];         // fc1 split-k partials (deterministic, no atomics)
__device__ float d_emb[MROWS * EE];             // gathered embeddings, row r = s*64+b
__device__ float d_gpre[MROWS * GG];            // precomputed gate inputs (+ both biases)
__device__ float d_Hall[MROWS * HH];            // h_t history (also fc2 A matrix)
__device__ float d_cbuf[2][BB * HH];            // double-buffered cell state
__device__ float d_logits[MROWS * VV];          // fc2 output (pre-softmax)
__device__ int   d_labels[TT * BB];             // normalized int32 labels

// -------------------- label decode (int32 vs int64 robust) ------------------
__global__ void k_decode(const int* __restrict__ lab) {
    __shared__ int is64;
    if (threadIdx.x == 0) {
        int f = 1;
        for (int i = 1; i < 64 && f; i += 2)
            if (lab[i] != 0) f = 0;   // int64 non-negative => odd words zero
        is64 = f;
    }
    __syncthreads();
    for (int i = threadIdx.x; i < TT * BB; i += blockDim.x) {
        d_labels[i] = is64 ? (int)(((const long long*)lab)[i]) : lab[i];
    }
}

__global__ void k_init() {
    int i = blockIdx.x * 256 + threadIdx.x;
    if (i < BB * HH) d_cbuf[0][i] = 0.f;
}

// -------------------- fc1: Xp = X @ fc1_w.T + b (split-K) -------------------
// grid (8 h-tiles of 32, 16 k-slices of 256), 256 threads
__global__ void __launch_bounds__(256) k_fc1(const float* __restrict__ X,
                                             const float* __restrict__ W) {
    const int h0 = blockIdx.x * 32;
    const int kb = blockIdx.y;
    const int kbase = kb * 256;
    const int tid = threadIdx.x;
    __shared__ __align__(16) float Xs[32][68];
    __shared__ float Wsh[32][33];
    float acc[4][2];
#pragma unroll
    for (int q = 0; q < 4; q++) { acc[q][0] = 0.f; acc[q][1] = 0.f; }
    const int tb = (tid & 15) * 4;   // batch base (0..60)
    const int th = (tid >> 4) * 2;   // h base within tile (0..30)

    for (int t = 0; t < 8; t++) {
        int k0 = kbase + t * 32;
#pragma unroll
        for (int i = 0; i < 8; i++) {
            int idx = tid + i * 256;               // 0..2047
            int b = idx >> 5, kk = idx & 31;
            Xs[kk][b] = X[(size_t)b * FF + k0 + kk];
        }
#pragma unroll
        for (int i = 0; i < 4; i++) {
            int idx = tid + i * 256;               // 0..1023
            int hh = idx >> 5, kk = idx & 31;
            Wsh[kk][hh] = W[(size_t)(h0 + hh) * FF + k0 + kk];
        }
        __syncthreads();
#pragma unroll
        for (int kk = 0; kk < 32; kk++) {
            float4 x4 = *(const float4*)&Xs[kk][tb];
            float w0 = Wsh[kk][th], w1 = Wsh[kk][th + 1];
            acc[0][0] += x4.x * w0; acc[0][1] += x4.x * w1;
            acc[1][0] += x4.y * w0; acc[1][1] += x4.y * w1;
            acc[2][0] += x4.z * w0; acc[2][1] += x4.z * w1;
            acc[3][0] += x4.w * w0; acc[3][1] += x4.w * w1;
        }
        __syncthreads();
    }
#pragma unroll
    for (int q = 0; q < 4; q++)
#pragma unroll
        for (int j = 0; j < 2; j++)
            d_xpart[kb * (BB * HH) + (tb + q) * HH + h0 + th + j] = acc[q][j];
}

__global__ void k_fc1red(const float* __restrict__ fc1_b) {
    int i = blockIdx.x * 256 + threadIdx.x;
    if (i < BB * HH) {
        float s = fc1_b[i & (HH - 1)];
#pragma unroll
        for (int kb = 0; kb < 16; kb++) s += d_xpart[kb * (BB * HH) + i];
        d_Xp[i] = s;
    }
}

// -------------------- gather embeddings -------------------------------------
__global__ void k_gather(const float* __restrict__ emb_table) {
    int r = blockIdx.x;                 // 0..1983
    int s = r >> 6, b = r & 63;
    int tok = (s == 0) ? 1 : d_labels[s * BB + b];   // START_ID = 1
    const float* src = emb_table + (size_t)tok * EE;
    float* dst = d_emb + (size_t)r * EE;
    for (int e = threadIdx.x; e < EE; e += blockDim.x) dst[e] = src[e];
}

// -------------------- Gpre GEMM: (1984 x 1024, K=556) -----------------------
// A virtual: A[r][k] = k<256 ? Xp[r&63][k] : emb[r][k-256]
__global__ void __launch_bounds__(256) k_gpre(const float* __restrict__ wih,
                                              const float* __restrict__ bih,
                                              const float* __restrict__ bhh) {
    __shared__ __align__(16) float As[2][8][132];
    __shared__ __align__(16) float Bs[2][8][132];
    const int tid = threadIdx.x;
    const int mrow = blockIdx.y * 128, ncol = blockIdx.x * 128;
    const int tx = tid & 15, ty = tid >> 4;
    const int lr = tid >> 1, lk = (tid & 1) * 4;
    float acc[8][8];
#pragma unroll
    for (int i = 0; i < 8; i++)
#pragma unroll
        for (int j = 0; j < 8; j++) acc[i][j] = 0.f;

    const int m = mrow + lr;
    const int n = ncol + lr;
    const int NT = 70;  // ceil(556/8)

    // preload tile 0
#pragma unroll
    for (int i = 0; i < 4; i++) {
        int k = lk + i;
        float va = 0.f;
        if (m < MROWS && k < KIN)
            va = (k < HH) ? d_Xp[(m & 63) * HH + k] : d_emb[(size_t)m * EE + (k - HH)];
        As[0][lk + i][lr] = va;
        Bs[0][lk + i][lr] = (k < KIN) ? wih[(size_t)n * KIN + k] : 0.f;
    }
    __syncthreads();

    for (int t = 0; t < NT; t++) {
        int cur = t & 1;
        if (t + 1 < NT) {
            int k0 = (t + 1) * 8;
#pragma unroll
            for (int i = 0; i < 4; i++) {
                int k = k0 + lk + i;
                float va = 0.f;
                if (m < MROWS && k < KIN)
                    va = (k < HH) ? d_Xp[(m & 63) * HH + k] : d_emb[(size_t)m * EE + (k - HH)];
                As[cur ^ 1][lk + i][lr] = va;
                Bs[cur ^ 1][lk + i][lr] = (k < KIN) ? wih[(size_t)n * KIN + k] : 0.f;
            }
        }
#pragma unroll
        for (int kk = 0; kk < 8; kk++) {
            float4 a0 = *(const float4*)&As[cur][kk][ty * 8];
            float4 a1 = *(const float4*)&As[cur][kk][ty * 8 + 4];
            float4 b0 = *(const float4*)&Bs[cur][kk][tx * 8];
            float4 b1 = *(const float4*)&Bs[cur][kk][tx * 8 + 4];
            float am[8] = {a0.x, a0.y, a0.z, a0.w, a1.x, a1.y, a1.z, a1.w};
            float bn[8] = {b0.x, b0.y, b0.z, b0.w, b1.x, b1.y, b1.z, b1.w};
#pragma unroll
            for (int i = 0; i < 8; i++)
#pragma unroll
                for (int j = 0; j < 8; j++) acc[i][j] += am[i] * bn[j];
        }
        __syncthreads();
    }
#pragma unroll
    for (int i = 0; i < 8; i++) {
        int mm = mrow + ty * 8 + i;
        if (mm >= MROWS) continue;
#pragma unroll
        for (int j = 0; j < 8; j++) {
            int nn = ncol + tx * 8 + j;
            d_gpre[(size_t)mm * GG + nn] = acc[i][j] + bih[nn] + bhh[nn];
        }
    }
}

// -------------------- per-step recurrence (gates GEMM + fused cell) ---------
// grid (16 j-tiles of 16, 4 b-tiles of 16), 256 threads.
// Block computes gates[b0..b0+15][{i,f,g,o} x (j0..j0+15)] then applies cell.
__global__ void __launch_bounds__(256) k_step(const float* __restrict__ w_hh, int s) {
    const int j0 = blockIdx.x * 16;
    const int b0 = blockIdx.y * 16;
    const int tid = threadIdx.x;
    __shared__ __align__(16) float Hs[2][16][17];
    __shared__ __align__(16) float Ws[2][16][68];
    __shared__ float gbuf[16][65];
    float acc[4] = {0.f, 0.f, 0.f, 0.f};
    const int tx = tid & 15;   // col group: cols tx*4..tx*4+3 (of 64 = 4 gates x 16 j)
    const int ty = tid >> 4;   // b index within tile

    if (s > 0) {
        const float* hprev = d_Hall + (size_t)(s - 1) * BB * HH;
        // preload k-tile 0
        {
            int bb = tid >> 4, kk = tid & 15;
            Hs[0][kk][bb] = hprev[(b0 + bb) * HH + kk];
#pragma unroll
            for (int i = 0; i < 4; i++) {
                int idx = tid + i * 256;
                int c = idx >> 4, kk2 = idx & 15;
                int r = ((c >> 4) << 8) + j0 + (c & 15);
                Ws[0][kk2][c] = w_hh[(size_t)r * HH + kk2];
            }
        }
        __syncthreads();
        for (int t = 0; t < 16; t++) {
            int cur = t & 1;
            if (t < 15) {
                int k0 = (t + 1) * 16;
                int bb = tid >> 4, kk = tid & 15;
                Hs[cur ^ 1][kk][bb] = hprev[(b0 + bb) * HH + k0 + kk];
#pragma unroll
                for (int i = 0; i < 4; i++) {
                    int idx = tid + i * 256;
                    int c = idx >> 4, kk2 = idx & 15;
                    int r = ((c >> 4) << 8) + j0 + (c & 15);
                    Ws[cur ^ 1][kk2][c] = w_hh[(size_t)r * HH + k0 + kk2];
                }
            }
#pragma unroll
            for (int kk = 0; kk < 16; kk++) {
                float h = Hs[cur][kk][ty];
                float4 w = *(const float4*)&Ws[cur][kk][tx * 4];
                acc[0] += h * w.x; acc[1] += h * w.y;
                acc[2] += h * w.z; acc[3] += h * w.w;
            }
            __syncthreads();
        }
    }

    // add Gpre, exchange through smem, apply LSTM cell
    {
        const float* gp = d_gpre + ((size_t)s * BB + b0) * GG;
#pragma unroll
        for (int q = 0; q < 4; q++) {
            int c = tx * 4 + q;
            int r = ((c >> 4) << 8) + j0 + (c & 15);
            gbuf[ty][c] = acc[q] + gp[(size_t)ty * GG + r];
        }
    }
    __syncthreads();
    {
        int bb = tid >> 4, jj = tid & 15;
        float gi = gbuf[bb][jj];
        float gf = gbuf[bb][16 + jj];
        float gg = gbuf[bb][32 + jj];
        float go = gbuf[bb][48 + jj];
        float ii = 1.f / (1.f + expf(-gi));
        float ff = 1.f / (1.f + expf(-gf));
        float g  = tanhf(gg);
        float oo = 1.f / (1.f + expf(-go));
        int cidx = (b0 + bb) * HH + j0 + jj;
        float cold = d_cbuf[s & 1][cidx];
        float cnew = ff * cold + ii * g;
        d_cbuf[(s + 1) & 1][cidx] = cnew;
        d_Hall[(size_t)s * BB * HH + cidx] = oo * tanhf(cnew);
    }
}

// -------------------- fc2 GEMM: logits (1984 x 10000, K=256) ----------------
__global__ void __launch_bounds__(256) k_fc2(const float* __restrict__ Wf,
                                             const float* __restrict__ bf) {
    __shared__ __align__(16) float As[2][8][132];
    __shared__ __align__(16) float Bs[2][8][132];
    const int tid = threadIdx.x;
    const int mrow = blockIdx.y * 128, ncol = blockIdx.x * 128;
    const int tx = tid & 15, ty = tid >> 4;
    const int lr = tid >> 1, lk = (tid & 1) * 4;
    float acc[8][8];
#pragma unroll
    for (int i = 0; i < 8; i++)
#pragma unroll
        for (int j = 0; j < 8; j++) acc[i][j] = 0.f;

    const int m = mrow + lr;
    const int n = ncol + lr;
    const bool mok = (m < MROWS);
    const bool nok = (n < VV);
    const int NT = 32;  // 256/8

    {
        float4 a = mok ? *(const float4*)(d_Hall + (size_t)m * HH + lk)
                       : make_float4(0.f, 0.f, 0.f, 0.f);
        float4 b = nok ? *(const float4*)(Wf + (size_t)n * HH + lk)
                       : make_float4(0.f, 0.f, 0.f, 0.f);
        As[0][lk + 0][lr] = a.x; As[0][lk + 1][lr] = a.y;
        As[0][lk + 2][lr] = a.z; As[0][lk + 3][lr] = a.w;
        Bs[0][lk + 0][lr] = b.x; Bs[0][lk + 1][lr] = b.y;
        Bs[0][lk + 2][lr] = b.z; Bs[0][lk + 3][lr] = b.w;
    }
    __syncthreads();

    for (int t = 0; t < NT; t++) {
        int cur = t & 1;
        if (t + 1 < NT) {
            int k0 = (t + 1) * 8;
            float4 a = mok ? *(const float4*)(d_Hall + (size_t)m * HH + k0 + lk)
                           : make_float4(0.f, 0.f, 0.f, 0.f);
            float4 b = nok ? *(const float4*)(Wf + (size_t)n * HH + k0 + lk)
                           : make_float4(0.f, 0.f, 0.f, 0.f);
            As[cur ^ 1][lk + 0][lr] = a.x; As[cur ^ 1][lk + 1][lr] = a.y;
            As[cur ^ 1][lk + 2][lr] = a.z; As[cur ^ 1][lk + 3][lr] = a.w;
            Bs[cur ^ 1][lk + 0][lr] = b.x; Bs[cur ^ 1][lk + 1][lr] = b.y;
            Bs[cur ^ 1][lk + 2][lr] = b.z; Bs[cur ^ 1][lk + 3][lr] = b.w;
        }
#pragma unroll
        for (int kk = 0; kk < 8; kk++) {
            float4 a0 = *(const float4*)&As[cur][kk][ty * 8];
            float4 a1 = *(const float4*)&As[cur][kk][ty * 8 + 4];
            float4 b0 = *(const float4*)&Bs[cur][kk][tx * 8];
            float4 b1 = *(const float4*)&Bs[cur][kk][tx * 8 + 4];
            float am[8] = {a0.x, a0.y, a0.z, a0.w, a1.x, a1.y, a1.z, a1.w};
            float bn[8] = {b0.x, b0.y, b0.z, b0.w, b1.x, b1.y, b1.z, b1.w};
#pragma unroll
            for (int i = 0; i < 8; i++)
#pragma unroll
                for (int j = 0; j < 8; j++) acc[i][j] += am[i] * bn[j];
        }
        __syncthreads();
    }
#pragma unroll
    for (int i = 0; i < 8; i++) {
        int mm = mrow + ty * 8 + i;
        if (mm >= MROWS) continue;
#pragma unroll
        for (int j = 0; j < 8; j++) {
            int nn = ncol + tx * 8 + j;
            if (nn < VV) d_logits[(size_t)mm * VV + nn] = acc[i][j] + bf[nn];
        }
    }
}

// -------------------- output: t=0 one-hot plane ------------------------------
__global__ void k_fill(float* __restrict__ out) {
    int b = blockIdx.x;
    float* dst = out + (size_t)b * TT * VV;
    for (int v = threadIdx.x; v < VV; v += blockDim.x)
        dst[v] = (v == 1) ? 1.f : 0.f;
}

// -------------------- log-softmax + transposed write ------------------------
__global__ void __launch_bounds__(256) k_softmax(float* __restrict__ out) {
    const int r = blockIdx.x;           // 0..1983
    const int s = r >> 6, b = r & 63;
    const int tid = threadIdx.x;
    __shared__ float rowbuf[VV];
    __shared__ float red[256];
    const float* src = d_logits + (size_t)r * VV;

    float mx = -1e30f;
    for (int v = tid; v < VV; v += 256) {
        float x = src[v];
        rowbuf[v] = x;
        mx = fmaxf(mx, x);
    }
    red[tid] = mx;
    __syncthreads();
    for (int o = 128; o > 0; o >>= 1) {
        if (tid < o) red[tid] = fmaxf(red[tid], red[tid + o]);
        __syncthreads();
    }
    mx = red[0];
    __syncthreads();

    float sum = 0.f;
    for (int v = tid; v < VV; v += 256) sum += expf(rowbuf[v] - mx);
    red[tid] = sum;
    __syncthreads();
    for (int o = 128; o > 0; o >>= 1) {
        if (tid < o) red[tid] += red[tid + o];
        __syncthreads();
    }
    float lz = mx + logf(red[0]);

    float* dst = out + ((size_t)b * TT + (s + 1)) * VV;
    for (int v = tid; v < VV; v += 256) dst[v] = rowbuf[v] - lz;
}

// -------------------- launch ------------------------------------------------
extern "C" void kernel_launch(void* const* d_in, const int* in_sizes, int n_in,
                              void* d_out, int out_size) {
    const float* X    = (const float*)d_in[0];
    const float* emb  = (const float*)d_in[1];
    const float* fc1w = (const float*)d_in[2];
    const float* fc1b = (const float*)d_in[3];
    const float* wih  = (const float*)d_in[4];
    const float* whh  = (const float*)d_in[5];
    const float* bih  = (const float*)d_in[6];
    const float* bhh  = (const float*)d_in[7];
    const float* fc2w = (const float*)d_in[8];
    const float* fc2b = (const float*)d_in[9];
    const int*   lab  = (const int*)d_in[10];
    float* out = (float*)d_out;

    k_decode<<<1, 256>>>(lab);
    k_init<<<64, 256>>>();
    k_fc1<<<dim3(8, 16), 256>>>(X, fc1w);
    k_fc1red<<<64, 256>>>(fc1b);
    k_gather<<<MROWS, 128>>>(emb);
    k_gpre<<<dim3(8, 16), 256>>>(wih, bih, bhh);
    for (int s = 0; s < SS; s++)
        k_step<<<dim3(16, 4), 256>>>(whh, s);
    k_fc2<<<dim3(79, 16), 256>>>(fc2w, fc2b);
    k_fill<<<64, 256>>>(out);
    k_softmax<<<MROWS, 256>>>(out);
}

// round 2
// speedup vs baseline: 1.6310x; 1.6310x over previous
#include <cuda_runtime.h>
#include <math.h>
#include <stdint.h>

// Problem dims
constexpr int BB = 64;     // batch
constexpr int TT = 32;     // sentence len
constexpr int SS = 31;     // scan steps (T-1)
constexpr int VV = 10000;  // vocab
constexpr int EE = 300;    // embed dim
constexpr int HH = 256;    // hidden
constexpr int FF = 4096;   // input features
constexpr int GG = 1024;   // 4*H gates
constexpr int KIN = HH + EE;   // 556
constexpr int KAP = 576;       // KIN padded to 16-multiple (and 4-float chunks)
constexpr int MROWS = SS * BB; // 1984

// -------------------- device scratch (static, no allocs) --------------------
__device__ float d_Xp[BB * HH];                 // fc1 output
__device__ float d_xpart[16 * BB * HH];         // fc1 split-k partials
__device__ float d_Acat[MROWS * KAP];           // [Xp | emb | 0pad] rows for gpre GEMM
__device__ float d_bias2[GG];                   // b_ih + b_hh
__device__ float d_gpre[MROWS * GG];            // precomputed gate inputs (+ both biases)
__device__ float d_Hall[MROWS * HH];            // h_t history (also fc2 A matrix)
__device__ float d_cbuf[2][BB * HH];            // double-buffered cell state
__device__ float d_logits[MROWS * VV];          // fc2 output (pre-softmax)
__device__ int   d_labels[TT * BB];             // normalized int32 labels

// -------------------- small helpers -----------------------------------------
__device__ __forceinline__ void cp16(void* smem_dst, const void* gsrc, bool pred) {
    uint32_t saddr = (uint32_t)__cvta_generic_to_shared(smem_dst);
    int sz = pred ? 16 : 0;
    asm volatile("cp.async.cg.shared.global [%0], [%1], 16, %2;\n"
                 :: "r"(saddr), "l"(gsrc), "r"(sz) : "memory");
}
__device__ __forceinline__ uint32_t f2tf(float x) {
    uint32_t r;
    asm("cvt.rna.tf32.f32 %0, %1;" : "=r"(r) : "f"(x));
    return r;
}
__device__ __forceinline__ void mma_tf32(float* d, const uint32_t* a, const uint32_t* b) {
    asm volatile(
        "mma.sync.aligned.m16n8k8.row.col.f32.tf32.tf32.f32 "
        "{%0,%1,%2,%3}, {%4,%5,%6,%7}, {%8,%9}, {%0,%1,%2,%3};"
        : "+f"(d[0]), "+f"(d[1]), "+f"(d[2]), "+f"(d[3])
        : "r"(a[0]), "r"(a[1]), "r"(a[2]), "r"(a[3]), "r"(b[0]), "r"(b[1]));
}

// -------------------- label decode (int32 vs int64 robust) ------------------
__global__ void k_decode(const int* __restrict__ lab) {
    __shared__ int is64;
    if (threadIdx.x == 0) {
        int f = 1;
        for (int i = 1; i < 64 && f; i += 2)
            if (lab[i] != 0) f = 0;
        is64 = f;
    }
    __syncthreads();
    for (int i = threadIdx.x; i < TT * BB; i += blockDim.x)
        d_labels[i] = is64 ? (int)(((const long long*)lab)[i]) : lab[i];
}

__global__ void k_init() {
    int i = blockIdx.x * 256 + threadIdx.x;
    if (i < BB * HH) d_cbuf[0][i] = 0.f;
}

// -------------------- fc1: Xp = X @ fc1_w.T + b (split-K SIMT) --------------
__global__ void __launch_bounds__(256) k_fc1(const float* __restrict__ X,
                                             const float* __restrict__ W) {
    const int h0 = blockIdx.x * 32;
    const int kb = blockIdx.y;
    const int kbase = kb * 256;
    const int tid = threadIdx.x;
    __shared__ __align__(16) float Xs[32][68];
    __shared__ float Wsh[32][33];
    float acc[4][2];
#pragma unroll
    for (int q = 0; q < 4; q++) { acc[q][0] = 0.f; acc[q][1] = 0.f; }
    const int tb = (tid & 15) * 4;
    const int th = (tid >> 4) * 2;

    for (int t = 0; t < 8; t++) {
        int k0 = kbase + t * 32;
#pragma unroll
        for (int i = 0; i < 8; i++) {
            int idx = tid + i * 256;
            int b = idx >> 5, kk = idx & 31;
            Xs[kk][b] = X[(size_t)b * FF + k0 + kk];
        }
#pragma unroll
        for (int i = 0; i < 4; i++) {
            int idx = tid + i * 256;
            int hh = idx >> 5, kk = idx & 31;
            Wsh[kk][hh] = W[(size_t)(h0 + hh) * FF + k0 + kk];
        }
        __syncthreads();
#pragma unroll
        for (int kk = 0; kk < 32; kk++) {
            float4 x4 = *(const float4*)&Xs[kk][tb];
            float w0 = Wsh[kk][th], w1 = Wsh[kk][th + 1];
            acc[0][0] += x4.x * w0; acc[0][1] += x4.x * w1;
            acc[1][0] += x4.y * w0; acc[1][1] += x4.y * w1;
            acc[2][0] += x4.z * w0; acc[2][1] += x4.z * w1;
            acc[3][0] += x4.w * w0; acc[3][1] += x4.w * w1;
        }
        __syncthreads();
    }
#pragma unroll
    for (int q = 0; q < 4; q++)
#pragma unroll
        for (int j = 0; j < 2; j++)
            d_xpart[kb * (BB * HH) + (tb + q) * HH + h0 + th + j] = acc[q][j];
}

__global__ void k_fc1red(const float* __restrict__ fc1_b) {
    int i = blockIdx.x * 256 + threadIdx.x;
    if (i < BB * HH) {
        float s = fc1_b[i & (HH - 1)];
#pragma unroll
        for (int kb = 0; kb < 16; kb++) s += d_xpart[kb * (BB * HH) + i];
        d_Xp[i] = s;
    }
}

// -------------------- build A = [Xp | emb | 0] rows --------------------------
__global__ void k_buildA(const float* __restrict__ emb_table) {
    int r = blockIdx.x;
    int s = r >> 6, b = r & 63;
    int tok = (s == 0) ? 1 : d_labels[s * BB + b];   // START_ID = 1
    const float* esrc = emb_table + (size_t)tok * EE;
    float* dst = d_Acat + (size_t)r * KAP;
    for (int i = threadIdx.x; i < KAP; i += blockDim.x) {
        float v;
        if (i < HH)       v = d_Xp[b * HH + i];
        else if (i < KIN) v = esrc[i - HH];
        else              v = 0.f;
        dst[i] = v;
    }
}

__global__ void k_bias2(const float* __restrict__ bih, const float* __restrict__ bhh) {
    int i = blockIdx.x * 256 + threadIdx.x;
    if (i < GG) d_bias2[i] = bih[i] + bhh[i];
}

// -------------------- generic tf32 tensor-core GEMM --------------------------
// C[M,N] = A[M,K] @ B[N,K]^T + bias[N]
// Block tile 128x128, BK=16, 8 warps (4M x 2N), warp tile 32x64, m16n8k8 tf32.
// K must be a multiple of 16; Ka/Kb give the valid (non-zero-fill) K extents.
__global__ void __launch_bounds__(256) k_tcgemm(
    const float* __restrict__ A, int lda,
    const float* __restrict__ B, int ldb,
    const float* __restrict__ bias,
    float* __restrict__ C, int ldc,
    int M, int N, int K, int Ka, int Kb)
{
    __shared__ float As[2][128][20];
    __shared__ float Bs[2][128][20];

    const int tid = threadIdx.x;
    const int lane = tid & 31;
    const int warpId = tid >> 5;
    const int warpM = warpId & 3;    // 0..3  -> 32 rows each
    const int warpN = warpId >> 2;   // 0..1  -> 64 cols each
    const int g = lane >> 2;         // 0..7
    const int t = lane & 3;          // 0..3

    const int ncol = blockIdx.x * 128;
    const int mrow = blockIdx.y * 128;

    float acc[2][8][4];
#pragma unroll
    for (int mt = 0; mt < 2; mt++)
#pragma unroll
        for (int nt = 0; nt < 8; nt++)
#pragma unroll
            for (int q = 0; q < 4; q++) acc[mt][nt][q] = 0.f;

    const int NT = K >> 4;

    // tile loader: 512 16B-chunks per matrix, 2 per thread each
    auto load_tile = [&](int buf, int kt) {
        int k0 = kt << 4;
#pragma unroll
        for (int i = 0; i < 2; i++) {
            int c = tid + i * 256;
            int m = c >> 2, kc = c & 3;
            const float* src = A + (size_t)(mrow + m) * lda + k0 + kc * 4;
            bool p = (mrow + m < M) && (k0 + kc * 4 < Ka);
            cp16(&As[buf][m][kc * 4], src, p);
        }
#pragma unroll
        for (int i = 0; i < 2; i++) {
            int c = tid + i * 256;
            int n = c >> 2, kc = c & 3;
            const float* src = B + (size_t)(ncol + n) * ldb + k0 + kc * 4;
            bool p = (ncol + n < N) && (k0 + kc * 4 < Kb);
            cp16(&Bs[buf][n][kc * 4], src, p);
        }
    };

    load_tile(0, 0);
    asm volatile("cp.async.commit_group;\n" ::: "memory");

    for (int kt = 0; kt < NT; kt++) {
        int buf = kt & 1;
        if (kt + 1 < NT) {
            load_tile(buf ^ 1, kt + 1);
            asm volatile("cp.async.commit_group;\n" ::: "memory");
            asm volatile("cp.async.wait_group 1;\n" ::: "memory");
        } else {
            asm volatile("cp.async.wait_group 0;\n" ::: "memory");
        }
        __syncthreads();

#pragma unroll
        for (int ks = 0; ks < 16; ks += 8) {
            uint32_t afr[2][4], bfr[8][2];
#pragma unroll
            for (int mt = 0; mt < 2; mt++) {
                int r0 = warpM * 32 + mt * 16;
                afr[mt][0] = f2tf(As[buf][r0 + g][ks + t]);
                afr[mt][1] = f2tf(As[buf][r0 + g + 8][ks + t]);
                afr[mt][2] = f2tf(As[buf][r0 + g][ks + t + 4]);
                afr[mt][3] = f2tf(As[buf][r0 + g + 8][ks + t + 4]);
            }
#pragma unroll
            for (int nt = 0; nt < 8; nt++) {
                int c0 = warpN * 64 + nt * 8;
                bfr[nt][0] = f2tf(Bs[buf][c0 + g][ks + t]);
                bfr[nt][1] = f2tf(Bs[buf][c0 + g][ks + t + 4]);
            }
#pragma unroll
            for (int mt = 0; mt < 2; mt++)
#pragma unroll
                for (int nt = 0; nt < 8; nt++)
                    mma_tf32(acc[mt][nt], afr[mt], bfr[nt]);
        }
        __syncthreads();
    }

    // epilogue: add bias, guarded stores (c0,c1 are adjacent columns)
#pragma unroll
    for (int mt = 0; mt < 2; mt++) {
#pragma unroll
        for (int nt = 0; nt < 8; nt++) {
            int m0 = mrow + warpM * 32 + mt * 16 + g;
            int n0 = ncol + warpN * 64 + nt * 8 + 2 * t;
            if (n0 < N) {
                float b0 = bias[n0], b1 = bias[n0 + 1];
                if (m0 < M) {
                    C[(size_t)m0 * ldc + n0]     = acc[mt][nt][0] + b0;
                    C[(size_t)m0 * ldc + n0 + 1] = acc[mt][nt][1] + b1;
                }
                if (m0 + 8 < M) {
                    C[(size_t)(m0 + 8) * ldc + n0]     = acc[mt][nt][2] + b0;
                    C[(size_t)(m0 + 8) * ldc + n0 + 1] = acc[mt][nt][3] + b1;
                }
            }
        }
    }
}

// -------------------- per-step recurrence (gates GEMM + fused cell) ---------
__global__ void __launch_bounds__(256) k_step(const float* __restrict__ w_hh, int s) {
    const int j0 = blockIdx.x * 16;
    const int b0 = blockIdx.y * 16;
    const int tid = threadIdx.x;
    __shared__ __align__(16) float Hs[2][16][17];
    __shared__ __align__(16) float Ws[2][16][68];
    __shared__ float gbuf[16][65];
    float acc[4] = {0.f, 0.f, 0.f, 0.f};
    const int tx = tid & 15;
    const int ty = tid >> 4;

    if (s > 0) {
        const float* hprev = d_Hall + (size_t)(s - 1) * BB * HH;
        {
            int bb = tid >> 4, kk = tid & 15;
            Hs[0][kk][bb] = hprev[(b0 + bb) * HH + kk];
#pragma unroll
            for (int i = 0; i < 4; i++) {
                int idx = tid + i * 256;
                int c = idx >> 4, kk2 = idx & 15;
                int r = ((c >> 4) << 8) + j0 + (c & 15);
                Ws[0][kk2][c] = w_hh[(size_t)r * HH + kk2];
            }
        }
        __syncthreads();
        for (int tk = 0; tk < 16; tk++) {
            int cur = tk & 1;
            if (tk < 15) {
                int k0 = (tk + 1) * 16;
                int bb = tid >> 4, kk = tid & 15;
                Hs[cur ^ 1][kk][bb] = hprev[(b0 + bb) * HH + k0 + kk];
#pragma unroll
                for (int i = 0; i < 4; i++) {
                    int idx = tid + i * 256;
                    int c = idx >> 4, kk2 = idx & 15;
                    int r = ((c >> 4) << 8) + j0 + (c & 15);
                    Ws[cur ^ 1][kk2][c] = w_hh[(size_t)r * HH + k0 + kk2];
                }
            }
#pragma unroll
            for (int kk = 0; kk < 16; kk++) {
                float h = Hs[cur][kk][ty];
                float4 w = *(const float4*)&Ws[cur][kk][tx * 4];
                acc[0] += h * w.x; acc[1] += h * w.y;
                acc[2] += h * w.z; acc[3] += h * w.w;
            }
            __syncthreads();
        }
    }

    {
        const float* gp = d_gpre + ((size_t)s * BB + b0) * GG;
#pragma unroll
        for (int q = 0; q < 4; q++) {
            int c = tx * 4 + q;
            int r = ((c >> 4) << 8) + j0 + (c & 15);
            gbuf[ty][c] = acc[q] + gp[(size_t)ty * GG + r];
        }
    }
    __syncthreads();
    {
        int bb = tid >> 4, jj = tid & 15;
        float gi = gbuf[bb][jj];
        float gf = gbuf[bb][16 + jj];
        float gg = gbuf[bb][32 + jj];
        float go = gbuf[bb][48 + jj];
        float ii = 1.f / (1.f + expf(-gi));
        float ff = 1.f / (1.f + expf(-gf));
        float g  = tanhf(gg);
        float oo = 1.f / (1.f + expf(-go));
        int cidx = (b0 + bb) * HH + j0 + jj;
        float cold = d_cbuf[s & 1][cidx];
        float cnew = ff * cold + ii * g;
        d_cbuf[(s + 1) & 1][cidx] = cnew;
        d_Hall[(size_t)s * BB * HH + cidx] = oo * tanhf(cnew);
    }
}

// -------------------- output: t=0 one-hot plane ------------------------------
__global__ void k_fill(float* __restrict__ out) {
    int b = blockIdx.x;
    float* dst = out + (size_t)b * TT * VV;
    for (int v = threadIdx.x; v < VV; v += blockDim.x)
        dst[v] = (v == 1) ? 1.f : 0.f;
}

// -------------------- log-softmax + transposed write ------------------------
__global__ void __launch_bounds__(256) k_softmax(float* __restrict__ out) {
    const int r = blockIdx.x;
    const int s = r >> 6, b = r & 63;
    const int tid = threadIdx.x;
    __shared__ float rowbuf[VV];
    __shared__ float red[256];
    const float* src = d_logits + (size_t)r * VV;

    float mx = -1e30f;
    for (int v = tid; v < VV; v += 256) {
        float x = src[v];
        rowbuf[v] = x;
        mx = fmaxf(mx, x);
    }
    red[tid] = mx;
    __syncthreads();
    for (int o = 128; o > 0; o >>= 1) {
        if (tid < o) red[tid] = fmaxf(red[tid], red[tid + o]);
        __syncthreads();
    }
    mx = red[0];
    __syncthreads();

    float sum = 0.f;
    for (int v = tid; v < VV; v += 256) sum += expf(rowbuf[v] - mx);
    red[tid] = sum;
    __syncthreads();
    for (int o = 128; o > 0; o >>= 1) {
        if (tid < o) red[tid] += red[tid + o];
        __syncthreads();
    }
    float lz = mx + logf(red[0]);

    float* dst = out + ((size_t)b * TT + (s + 1)) * VV;
    for (int v = tid; v < VV; v += 256) dst[v] = rowbuf[v] - lz;
}

// -------------------- launch ------------------------------------------------
extern "C" void kernel_launch(void* const* d_in, const int* in_sizes, int n_in,
                              void* d_out, int out_size) {
    const float* X    = (const float*)d_in[0];
    const float* emb  = (const float*)d_in[1];
    const float* fc1w = (const float*)d_in[2];
    const float* fc1b = (const float*)d_in[3];
    const float* wih  = (const float*)d_in[4];
    const float* whh  = (const float*)d_in[5];
    const float* bih  = (const float*)d_in[6];
    const float* bhh  = (const float*)d_in[7];
    const float* fc2w = (const float*)d_in[8];
    const float* fc2b = (const float*)d_in[9];
    const int*   lab  = (const int*)d_in[10];
    float* out = (float*)d_out;

    // pointers to device globals for GEMM args
    float *pAcat, *pBias2, *pGpre, *pHall, *pLogits;
    cudaGetSymbolAddress((void**)&pAcat,   d_Acat);
    cudaGetSymbolAddress((void**)&pBias2,  d_bias2);
    cudaGetSymbolAddress((void**)&pGpre,   d_gpre);
    cudaGetSymbolAddress((void**)&pHall,   d_Hall);
    cudaGetSymbolAddress((void**)&pLogits, d_logits);

    k_decode<<<1, 256>>>(lab);
    k_init<<<64, 256>>>();
    k_fc1<<<dim3(8, 16), 256>>>(X, fc1w);
    k_fc1red<<<64, 256>>>(fc1b);
    k_buildA<<<MROWS, 192>>>(emb);
    k_bias2<<<4, 256>>>(bih, bhh);

    // gpre: C[1984,1024] = Acat[1984,576] @ wih[1024,556]^T + (bih+bhh)
    k_tcgemm<<<dim3(8, 16), 256>>>(pAcat, KAP, wih, KIN, pBias2,
                                   pGpre, GG, MROWS, GG, KAP, KAP, KIN);

    for (int s = 0; s < SS; s++)
        k_step<<<dim3(16, 4), 256>>>(whh, s);

    // fc2: logits[1984,10000] = Hall[1984,256] @ fc2w[10000,256]^T + fc2b
    k_tcgemm<<<dim3(79, 16), 256>>>(pHall, HH, fc2w, HH, fc2b,
                                    pLogits, VV, MROWS, VV, HH, HH, HH);

    k_fill<<<64, 256>>>(out);
    k_softmax<<<MROWS, 256>>>(out);
}

// round 3
// speedup vs baseline: 2.4148x; 1.4806x over previous
#include <cuda_runtime.h>
#include <math.h>
#include <stdint.h>

// Problem dims
constexpr int BB = 64;
constexpr int TT = 32;
constexpr int SS = 31;     // scan steps (T-1)
constexpr int VV = 10000;
constexpr int EE = 300;
constexpr int HH = 256;
constexpr int FF = 4096;
constexpr int GG = 1024;   // 4*H
constexpr int KIN = HH + EE;   // 556
constexpr int KAP = 576;       // KIN padded to 16
constexpr int MROWS = SS * BB; // 1984
constexpr int RB = 16;         // persistent recurrence blocks

// -------------------- device scratch (static, no allocs) --------------------
__device__ float d_Xp[BB * HH];
__device__ float d_xpart[16 * BB * HH];
__device__ float d_Acat[MROWS * KAP];      // [Xp | emb | 0], tf32-rounded
__device__ float d_bias2[GG];              // b_ih + b_hh
__device__ float d_gpre[MROWS * GG];       // precomputed gate inputs
__device__ float d_Hall[MROWS * HH];       // h history, tf32-rounded (fc2 A)
__device__ float d_logits[MROWS * VV];
__device__ int   d_labels[TT * BB];
__device__ float d_w2tf[VV * HH];          // fc2_w pre-converted tf32
__device__ float d_wihtf[GG * KAP];        // w_ih pre-converted tf32, K-padded
__device__ unsigned bar_cnt = 0;
__device__ volatile unsigned bar_gen = 0;

// -------------------- helpers ------------------------------------------------
__device__ __forceinline__ void cp16(void* smem_dst, const void* gsrc, bool pred) {
    uint32_t saddr = (uint32_t)__cvta_generic_to_shared(smem_dst);
    int sz = pred ? 16 : 0;
    asm volatile("cp.async.cg.shared.global [%0], [%1], 16, %2;\n"
                 :: "r"(saddr), "l"(gsrc), "r"(sz) : "memory");
}
__device__ __forceinline__ uint32_t f2tf(float x) {
    uint32_t r;
    asm("cvt.rna.tf32.f32 %0, %1;" : "=r"(r) : "f"(x));
    return r;
}
__device__ __forceinline__ void mma_tf32(float* d, const uint32_t* a, const uint32_t* b) {
    asm volatile(
        "mma.sync.aligned.m16n8k8.row.col.f32.tf32.tf32.f32 "
        "{%0,%1,%2,%3}, {%4,%5,%6,%7}, {%8,%9}, {%0,%1,%2,%3};"
        : "+f"(d[0]), "+f"(d[1]), "+f"(d[2]), "+f"(d[3])
        : "r"(a[0]), "r"(a[1]), "r"(a[2]), "r"(a[3]), "r"(b[0]), "r"(b[1]));
}

// -------------------- label decode -------------------------------------------
__global__ void k_decode(const int* __restrict__ lab) {
    __shared__ int is64;
    if (threadIdx.x == 0) {
        int f = 1;
        for (int i = 1; i < 64 && f; i += 2)
            if (lab[i] != 0) f = 0;
        is64 = f;
    }
    __syncthreads();
    for (int i = threadIdx.x; i < TT * BB; i += blockDim.x)
        d_labels[i] = is64 ? (int)(((const long long*)lab)[i]) : lab[i];
}

// -------------------- fc1: Xp = X @ fc1_w.T + b (split-K SIMT) ---------------
__global__ void __launch_bounds__(256) k_fc1(const float* __restrict__ X,
                                             const float* __restrict__ W) {
    const int h0 = blockIdx.x * 32;
    const int kb = blockIdx.y;
    const int kbase = kb * 256;
    const int tid = threadIdx.x;
    __shared__ __align__(16) float Xs[32][68];
    __shared__ float Wsh[32][33];
    float acc[4][2];
#pragma unroll
    for (int q = 0; q < 4; q++) { acc[q][0] = 0.f; acc[q][1] = 0.f; }
    const int tb = (tid & 15) * 4;
    const int th = (tid >> 4) * 2;

    for (int t = 0; t < 8; t++) {
        int k0 = kbase + t * 32;
#pragma unroll
        for (int i = 0; i < 8; i++) {
            int idx = tid + i * 256;
            int b = idx >> 5, kk = idx & 31;
            Xs[kk][b] = X[(size_t)b * FF + k0 + kk];
        }
#pragma unroll
        for (int i = 0; i < 4; i++) {
            int idx = tid + i * 256;
            int hh = idx >> 5, kk = idx & 31;
            Wsh[kk][hh] = W[(size_t)(h0 + hh) * FF + k0 + kk];
        }
        __syncthreads();
#pragma unroll
        for (int kk = 0; kk < 32; kk++) {
            float4 x4 = *(const float4*)&Xs[kk][tb];
            float w0 = Wsh[kk][th], w1 = Wsh[kk][th + 1];
            acc[0][0] += x4.x * w0; acc[0][1] += x4.x * w1;
            acc[1][0] += x4.y * w0; acc[1][1] += x4.y * w1;
            acc[2][0] += x4.z * w0; acc[2][1] += x4.z * w1;
            acc[3][0] += x4.w * w0; acc[3][1] += x4.w * w1;
        }
        __syncthreads();
    }
#pragma unroll
    for (int q = 0; q < 4; q++)
#pragma unroll
        for (int j = 0; j < 2; j++)
            d_xpart[kb * (BB * HH) + (tb + q) * HH + h0 + th + j] = acc[q][j];
}

__global__ void k_fc1red(const float* __restrict__ fc1_b) {
    int i = blockIdx.x * 256 + threadIdx.x;
    if (i < BB * HH) {
        float s = fc1_b[i & (HH - 1)];
#pragma unroll
        for (int kb = 0; kb < 16; kb++) s += d_xpart[kb * (BB * HH) + i];
        d_Xp[i] = s;
    }
}

// -------------------- build A = [Xp | emb | 0] (tf32-rounded) ----------------
__global__ void k_buildA(const float* __restrict__ emb_table) {
    int r = blockIdx.x;
    int s = r >> 6, b = r & 63;
    int tok = (s == 0) ? 1 : d_labels[s * BB + b];   // START_ID = 1
    const float* esrc = emb_table + (size_t)tok * EE;
    float* dst = d_Acat + (size_t)r * KAP;
    for (int i = threadIdx.x; i < KAP; i += blockDim.x) {
        float v;
        if (i < HH)       v = d_Xp[b * HH + i];
        else if (i < KIN) v = esrc[i - HH];
        else              v = 0.f;
        dst[i] = __uint_as_float(f2tf(v));
    }
}

__global__ void k_bias2(const float* __restrict__ bih, const float* __restrict__ bhh) {
    int i = blockIdx.x * 256 + threadIdx.x;
    if (i < GG) d_bias2[i] = bih[i] + bhh[i];
}

// -------------------- tf32 pre-conversion kernels ----------------------------
__global__ void k_cvt2(const float* __restrict__ w) {
    size_t i = (size_t)blockIdx.x * 256 + threadIdx.x;
    if (i < (size_t)VV * HH) d_w2tf[i] = __uint_as_float(f2tf(w[i]));
}
__global__ void k_cvtwih(const float* __restrict__ w) {
    int i = blockIdx.x * 256 + threadIdx.x;
    if (i < GG * KAP) {
        int r = i / KAP, k = i - r * KAP;
        d_wihtf[i] = (k < KIN) ? __uint_as_float(f2tf(w[r * KIN + k])) : 0.f;
    }
}

// -------------------- generic tf32 GEMM (inputs pre-converted) ---------------
// C[M,N] = A[M,K] @ B[N,K]^T + bias[N]; 128x128 tile, BK=16, 8 warps
__global__ void __launch_bounds__(256) k_tcgemm(
    const float* __restrict__ A, int lda,
    const float* __restrict__ B, int ldb,
    const float* __restrict__ bias,
    float* __restrict__ C, int ldc,
    int M, int N, int K, int Ka, int Kb)
{
    __shared__ float As[2][128][20];
    __shared__ float Bs[2][128][20];

    const int tid = threadIdx.x;
    const int lane = tid & 31;
    const int warpId = tid >> 5;
    const int warpM = warpId & 3;
    const int warpN = warpId >> 2;
    const int g = lane >> 2;
    const int t = lane & 3;

    const int ncol = blockIdx.x * 128;
    const int mrow = blockIdx.y * 128;

    float acc[2][8][4];
#pragma unroll
    for (int mt = 0; mt < 2; mt++)
#pragma unroll
        for (int nt = 0; nt < 8; nt++)
#pragma unroll
            for (int q = 0; q < 4; q++) acc[mt][nt][q] = 0.f;

    const int NT = K >> 4;

    auto load_tile = [&](int buf, int kt) {
        int k0 = kt << 4;
#pragma unroll
        for (int i = 0; i < 2; i++) {
            int c = tid + i * 256;
            int m = c >> 2, kc = c & 3;
            const float* src = A + (size_t)(mrow + m) * lda + k0 + kc * 4;
            bool p = (mrow + m < M) && (k0 + kc * 4 < Ka);
            cp16(&As[buf][m][kc * 4], src, p);
        }
#pragma unroll
        for (int i = 0; i < 2; i++) {
            int c = tid + i * 256;
            int n = c >> 2, kc = c & 3;
            const float* src = B + (size_t)(ncol + n) * ldb + k0 + kc * 4;
            bool p = (ncol + n < N) && (k0 + kc * 4 < Kb);
            cp16(&Bs[buf][n][kc * 4], src, p);
        }
    };

    load_tile(0, 0);
    asm volatile("cp.async.commit_group;\n" ::: "memory");

    for (int kt = 0; kt < NT; kt++) {
        int buf = kt & 1;
        if (kt + 1 < NT) {
            load_tile(buf ^ 1, kt + 1);
            asm volatile("cp.async.commit_group;\n" ::: "memory");
            asm volatile("cp.async.wait_group 1;\n" ::: "memory");
        } else {
            asm volatile("cp.async.wait_group 0;\n" ::: "memory");
        }
        __syncthreads();

#pragma unroll
        for (int ks = 0; ks < 16; ks += 8) {
            uint32_t afr[2][4], bfr[8][2];
#pragma unroll
            for (int mt = 0; mt < 2; mt++) {
                int r0 = warpM * 32 + mt * 16;
                afr[mt][0] = __float_as_uint(As[buf][r0 + g][ks + t]);
                afr[mt][1] = __float_as_uint(As[buf][r0 + g + 8][ks + t]);
                afr[mt][2] = __float_as_uint(As[buf][r0 + g][ks + t + 4]);
                afr[mt][3] = __float_as_uint(As[buf][r0 + g + 8][ks + t + 4]);
            }
#pragma unroll
            for (int nt = 0; nt < 8; nt++) {
                int c0 = warpN * 64 + nt * 8;
                bfr[nt][0] = __float_as_uint(Bs[buf][c0 + g][ks + t]);
                bfr[nt][1] = __float_as_uint(Bs[buf][c0 + g][ks + t + 4]);
            }
#pragma unroll
            for (int mt = 0; mt < 2; mt++)
#pragma unroll
                for (int nt = 0; nt < 8; nt++)
                    mma_tf32(acc[mt][nt], afr[mt], bfr[nt]);
        }
        __syncthreads();
    }

#pragma unroll
    for (int mt = 0; mt < 2; mt++) {
#pragma unroll
        for (int nt = 0; nt < 8; nt++) {
            int m0 = mrow + warpM * 32 + mt * 16 + g;
            int n0 = ncol + warpN * 64 + nt * 8 + 2 * t;
            if (n0 < N) {
                float b0 = bias[n0], b1 = bias[n0 + 1];
                if (m0 < M) {
                    C[(size_t)m0 * ldc + n0]     = acc[mt][nt][0] + b0;
                    C[(size_t)m0 * ldc + n0 + 1] = acc[mt][nt][1] + b1;
                }
                if (m0 + 8 < M) {
                    C[(size_t)(m0 + 8) * ldc + n0]     = acc[mt][nt][2] + b0;
                    C[(size_t)(m0 + 8) * ldc + n0 + 1] = acc[mt][nt][3] + b1;
                }
            }
        }
    }
}

// -------------------- persistent recurrence (tensor cores, w in registers) ---
// 16 blocks (one per 16-j slice), 256 threads, all co-resident. Grid barrier
// between steps. w_hh fragments preloaded to registers (tf32), h via smem.
__global__ void __launch_bounds__(256, 1) k_rec(const float* __restrict__ w_hh) {
    extern __shared__ float sm[];
    float* hs   = sm;               // [64][260] h_prev, padded
    float* gbuf = sm + 64 * 260;    // [64][68]  gate exchange

    const int tid = threadIdx.x;
    const int lane = tid & 31;
    const int wid = tid >> 5;
    const int mg = wid >> 2;    // 0..1  (rows mg*32..+31)
    const int ng = wid & 3;     // 0..3  (local cols ng*16..+15)
    const int g = lane >> 2;
    const int t = lane & 3;
    const int j0 = blockIdx.x * 16;

    // preload w_hh fragments (constant across all steps)
    uint32_t wb[2][32][2];
#pragma unroll
    for (int nt = 0; nt < 2; nt++) {
        int lc = ng * 16 + nt * 8 + g;
        int wrow = (lc >> 4) * 256 + j0 + (lc & 15);
        const float* wr = w_hh + (size_t)wrow * HH;
#pragma unroll
        for (int kt = 0; kt < 32; kt++) {
            wb[nt][kt][0] = f2tf(wr[kt * 8 + t]);
            wb[nt][kt][1] = f2tf(wr[kt * 8 + t + 4]);
        }
    }

    float creg[4] = {0.f, 0.f, 0.f, 0.f};   // cell state (thread-owned)
    unsigned mygen = bar_gen;
    const int cb = tid >> 2;           // cell batch row
    const int cj = (tid & 3) * 4;      // cell jj base

    for (int s = 0; s < SS; s++) {
        float acc[2][2][4];
#pragma unroll
        for (int mt = 0; mt < 2; mt++)
#pragma unroll
            for (int nt = 0; nt < 2; nt++)
#pragma unroll
                for (int q = 0; q < 4; q++) acc[mt][nt][q] = 0.f;

        if (s > 0) {
            const float4* src = (const float4*)(d_Hall + (size_t)(s - 1) * BB * HH);
#pragma unroll
            for (int i = 0; i < 16; i++) {
                int c = tid + i * 256;
                int m = c >> 6, kc = c & 63;
                *(float4*)&hs[m * 260 + kc * 4] = src[c];
            }
            __syncthreads();
#pragma unroll
            for (int kt = 0; kt < 32; kt++) {
                uint32_t af[2][4];
#pragma unroll
                for (int mt = 0; mt < 2; mt++) {
                    int r0 = mg * 32 + mt * 16;
                    af[mt][0] = __float_as_uint(hs[(r0 + g) * 260 + kt * 8 + t]);
                    af[mt][1] = __float_as_uint(hs[(r0 + g + 8) * 260 + kt * 8 + t]);
                    af[mt][2] = __float_as_uint(hs[(r0 + g) * 260 + kt * 8 + t + 4]);
                    af[mt][3] = __float_as_uint(hs[(r0 + g + 8) * 260 + kt * 8 + t + 4]);
                }
#pragma unroll
                for (int mt = 0; mt < 2; mt++)
#pragma unroll
                    for (int nt = 0; nt < 2; nt++)
                        mma_tf32(acc[mt][nt], af[mt], wb[nt][kt]);
            }
        }

        // gates = acc + gpre -> gbuf
        const float* gp = d_gpre + (size_t)s * BB * GG;
#pragma unroll
        for (int mt = 0; mt < 2; mt++) {
#pragma unroll
            for (int nt = 0; nt < 2; nt++) {
                int b0r = mg * 32 + mt * 16 + g;
                int lc0 = ng * 16 + nt * 8 + 2 * t;
                int r0 = (lc0 >> 4) * 256 + j0 + (lc0 & 15);
                float2 g0 = *(const float2*)&gp[(size_t)b0r * GG + r0];
                float2 g1 = *(const float2*)&gp[(size_t)(b0r + 8) * GG + r0];
                gbuf[b0r * 68 + lc0]           = acc[mt][nt][0] + g0.x;
                gbuf[b0r * 68 + lc0 + 1]       = acc[mt][nt][1] + g0.y;
                gbuf[(b0r + 8) * 68 + lc0]     = acc[mt][nt][2] + g1.x;
                gbuf[(b0r + 8) * 68 + lc0 + 1] = acc[mt][nt][3] + g1.y;
            }
        }
        __syncthreads();

        // LSTM cell (4 cells per thread), write tf32-rounded h
        float4 h4;
        const float* gb = gbuf + cb * 68;
#pragma unroll
        for (int q = 0; q < 4; q++) {
            int jj = cj + q;
            float gi = gb[jj], gf = gb[16 + jj], gc = gb[32 + jj], go = gb[48 + jj];
            float ii = 1.f / (1.f + expf(-gi));
            float ff = 1.f / (1.f + expf(-gf));
            float gv = tanhf(gc);
            float oo = 1.f / (1.f + expf(-go));
            float cn = ff * creg[q] + ii * gv;
            creg[q] = cn;
            float hv = oo * tanhf(cn);
            ((float*)&h4)[q] = __uint_as_float(f2tf(hv));
        }
        *(float4*)&d_Hall[((size_t)s * BB + cb) * HH + j0 + cj] = h4;

        // grid barrier (skip after last step)
        if (s + 1 < SS) {
            __threadfence();
            __syncthreads();
            if (tid == 0) {
                if (atomicInc(&bar_cnt, RB - 1) == RB - 1) {
                    bar_gen = mygen + 1;
                } else {
                    while (bar_gen == mygen) {}
                }
            }
            __syncthreads();
            mygen++;
        }
    }
}

// -------------------- output: t=0 one-hot plane ------------------------------
__global__ void k_fill(float* __restrict__ out) {
    int b = blockIdx.x;
    float* dst = out + (size_t)b * TT * VV;
    for (int v = threadIdx.x; v < VV; v += blockDim.x)
        dst[v] = (v == 1) ? 1.f : 0.f;
}

// -------------------- online log-softmax + transposed write ------------------
__global__ void __launch_bounds__(256) k_softmax(float* __restrict__ out) {
    const int r = blockIdx.x;
    const int s = r >> 6, b = r & 63;
    const int tid = threadIdx.x;
    const float4* src = (const float4*)(d_logits + (size_t)r * VV);

    float m = -1e30f, sum = 0.f;
    for (int c = tid; c < VV / 4; c += 256) {
        float4 x = src[c];
        float m4 = fmaxf(fmaxf(x.x, x.y), fmaxf(x.z, x.w));
        if (m4 > m) { sum *= expf(m - m4); m = m4; }
        sum += expf(x.x - m) + expf(x.y - m) + expf(x.z - m) + expf(x.w - m);
    }
#pragma unroll
    for (int o = 16; o; o >>= 1) {
        float mo = __shfl_xor_sync(0xffffffffu, m, o);
        float so = __shfl_xor_sync(0xffffffffu, sum, o);
        float M = fmaxf(m, mo);
        sum = sum * expf(m - M) + so * expf(mo - M);
        m = M;
    }
    __shared__ float sm_m[8], sm_s[8], s_lz;
    if ((tid & 31) == 0) { sm_m[tid >> 5] = m; sm_s[tid >> 5] = sum; }
    __syncthreads();
    if (tid == 0) {
        float M = sm_m[0], S = sm_s[0];
#pragma unroll
        for (int w = 1; w < 8; w++) {
            float mo = sm_m[w], so = sm_s[w];
            float MM = fmaxf(M, mo);
            S = S * expf(M - MM) + so * expf(mo - MM);
            M = MM;
        }
        s_lz = M + logf(S);
    }
    __syncthreads();
    float lz = s_lz;
    float4* dst = (float4*)(out + ((size_t)b * TT + s + 1) * VV);
    for (int c = tid; c < VV / 4; c += 256) {
        float4 x = src[c];
        x.x -= lz; x.y -= lz; x.z -= lz; x.w -= lz;
        dst[c] = x;
    }
}

// -------------------- launch ------------------------------------------------
extern "C" void kernel_launch(void* const* d_in, const int* in_sizes, int n_in,
                              void* d_out, int out_size) {
    const float* X    = (const float*)d_in[0];
    const float* emb  = (const float*)d_in[1];
    const float* fc1w = (const float*)d_in[2];
    const float* fc1b = (const float*)d_in[3];
    const float* wih  = (const float*)d_in[4];
    const float* whh  = (const float*)d_in[5];
    const float* bih  = (const float*)d_in[6];
    const float* bhh  = (const float*)d_in[7];
    const float* fc2w = (const float*)d_in[8];
    const float* fc2b = (const float*)d_in[9];
    const int*   lab  = (const int*)d_in[10];
    float* out = (float*)d_out;

    float *pAcat, *pBias2, *pGpre, *pHall, *pLogits, *pW2tf, *pWihtf;
    cudaGetSymbolAddress((void**)&pAcat,   d_Acat);
    cudaGetSymbolAddress((void**)&pBias2,  d_bias2);
    cudaGetSymbolAddress((void**)&pGpre,   d_gpre);
    cudaGetSymbolAddress((void**)&pHall,   d_Hall);
    cudaGetSymbolAddress((void**)&pLogits, d_logits);
    cudaGetSymbolAddress((void**)&pW2tf,   d_w2tf);
    cudaGetSymbolAddress((void**)&pWihtf,  d_wihtf);

    static int smem_set = 0;
    const int SMEMR = (64 * 260 + 64 * 68) * 4;   // 83968 B
    if (!smem_set) {
        cudaFuncSetAttribute(k_rec, cudaFuncAttributeMaxDynamicSharedMemorySize, SMEMR);
        smem_set = 1;
    }

    k_decode<<<1, 256>>>(lab);
    k_fc1<<<dim3(8, 16), 256>>>(X, fc1w);
    k_fc1red<<<64, 256>>>(fc1b);
    k_buildA<<<MROWS, 192>>>(emb);
    k_bias2<<<4, 256>>>(bih, bhh);
    k_cvt2<<<(VV * HH + 255) / 256, 256>>>(fc2w);
    k_cvtwih<<<(GG * KAP + 255) / 256, 256>>>(wih);

    // gpre: [1984,1024] = Acat[1984,576] @ wihtf[1024,576]^T + (bih+bhh)
    k_tcgemm<<<dim3(8, 16), 256>>>(pAcat, KAP, pWihtf, KAP, pBias2,
                                   pGpre, GG, MROWS, GG, KAP, KAP, KAP);

    // full recurrence in one persistent kernel
    k_rec<<<RB, 256, SMEMR>>>(whh);

    // fc2: logits[1984,10000] = Hall @ w2tf^T + fc2b
    k_tcgemm<<<dim3(79, 16), 256>>>(pHall, HH, pW2tf, HH, fc2b,
                                    pLogits, VV, MROWS, VV, HH, HH, HH);

    k_fill<<<64, 256>>>(out);
    k_softmax<<<MROWS, 256>>>(out);
}